// round 6
// baseline (speedup 1.0000x reference)
#include <cuda_runtime.h>
#include <math.h>
#include <stdint.h>

// Problem constants
#define BDIM   4
#define TDIM   2048
#define CDIM   1024
#define HEADS  16
#define HD     64
#define FFDIM  4096
#define BT     8192            // B*T rows
#define QKVW   3072            // 3*C

// ---------------------------------------------------------------------------
// Scratch (no allocations allowed — __device__ globals)
// ---------------------------------------------------------------------------
__device__ float g_ln [BT * CDIM];
__device__ float g_qkv[BT * QKVW];
__device__ float g_y  [BT * CDIM];
__device__ float g_x2 [BT * CDIM];
__device__ float g_h  [BT * FFDIM];
// tf32-rounded weights
__device__ float g_wq [QKVW * CDIM];
__device__ float g_wo [CDIM * CDIM];
__device__ float g_wfc[FFDIM * CDIM];
__device__ float g_wp [CDIM * FFDIM];

// ---------------------------------------------------------------------------
// Helpers
// ---------------------------------------------------------------------------
__device__ __forceinline__ uint32_t f2tf32(float f) {
    uint32_t u;
    asm("cvt.rna.tf32.f32 %0, %1;" : "=r"(u) : "f"(f));
    return u;
}
__device__ __forceinline__ float tf32r(float f) {
    return __uint_as_float(f2tf32(f));
}
__device__ __forceinline__ uint32_t smem_u32(const void* p) {
    uint32_t a;
    asm("{ .reg .u64 t; cvta.to.shared.u64 t, %1; cvt.u32.u64 %0, t; }"
        : "=r"(a) : "l"(p));
    return a;
}
__device__ __forceinline__ void cp_async16(uint32_t saddr, const void* gaddr) {
    asm volatile("cp.async.cg.shared.global [%0], [%1], 16;"
                 :: "r"(saddr), "l"(gaddr) : "memory");
}
__device__ __forceinline__ void cp_commit() {
    asm volatile("cp.async.commit_group;" ::: "memory");
}
__device__ __forceinline__ void mma_tf32(float* d, const uint32_t* a,
                                         uint32_t b0, uint32_t b1) {
    asm volatile(
        "mma.sync.aligned.m16n8k8.row.col.f32.tf32.tf32.f32 "
        "{%0,%1,%2,%3}, {%4,%5,%6,%7}, {%8,%9}, {%0,%1,%2,%3};"
        : "+f"(d[0]), "+f"(d[1]), "+f"(d[2]), "+f"(d[3])
        : "r"(a[0]), "r"(a[1]), "r"(a[2]), "r"(a[3]), "r"(b0), "r"(b1));
}
__device__ __forceinline__ float gelu_f(float v) {
    return 0.5f * v * (1.0f + erff(v * 0.70710678118654752f));
}

// ---------------------------------------------------------------------------
// Weight prep: round to tf32 once
// ---------------------------------------------------------------------------
__global__ __launch_bounds__(256)
void round_tf32_kernel(const float* __restrict__ src, float* __restrict__ dst,
                       int n4)
{
    const int i = blockIdx.x * blockDim.x + threadIdx.x;
    if (i < n4) {
        float4 v = ((const float4*)src)[i];
        v.x = tf32r(v.x); v.y = tf32r(v.y);
        v.z = tf32r(v.z); v.w = tf32r(v.w);
        ((float4*)dst)[i] = v;
    }
}

// ---------------------------------------------------------------------------
// LayerNorm: one block per row, C=1024, 256 threads x float4 (tf32 output)
// ---------------------------------------------------------------------------
__global__ __launch_bounds__(256)
void ln_kernel(const float* __restrict__ x, const float* __restrict__ g,
               float* __restrict__ y)
{
    const int row = blockIdx.x;
    const int tid = threadIdx.x;
    const float4 v = ((const float4*)(x + (size_t)row * CDIM))[tid];
    float s  = v.x + v.y + v.z + v.w;
    float ss = v.x * v.x + v.y * v.y + v.z * v.z + v.w * v.w;
#pragma unroll
    for (int o = 16; o > 0; o >>= 1) {
        s  += __shfl_xor_sync(0xffffffffu, s,  o);
        ss += __shfl_xor_sync(0xffffffffu, ss, o);
    }
    __shared__ float rs[8], rss[8];
    const int w = tid >> 5, lane = tid & 31;
    if (lane == 0) { rs[w] = s; rss[w] = ss; }
    __syncthreads();
    if (tid == 0) {
        float a = 0.f, b = 0.f;
#pragma unroll
        for (int i = 0; i < 8; i++) { a += rs[i]; b += rss[i]; }
        const float mean = a * (1.0f / CDIM);
        const float var  = b * (1.0f / CDIM) - mean * mean;
        rs[0]  = mean;
        rss[0] = rsqrtf(var + 1e-5f);
    }
    __syncthreads();
    const float mean = rs[0], rstd = rss[0];
    const float4 gv = ((const float4*)g)[tid];
    float4 o4;
    o4.x = tf32r((v.x - mean) * rstd * gv.x);
    o4.y = tf32r((v.y - mean) * rstd * gv.y);
    o4.z = tf32r((v.z - mean) * rstd * gv.z);
    o4.w = tf32r((v.w - mean) * rstd * gv.w);
    ((float4*)(y + (size_t)row * CDIM))[tid] = o4;
}

// ---------------------------------------------------------------------------
// TF32 mma.sync GEMM v3 (NT): C[m,n] = sum_k A[m,k]*B[n,k]
// CTA 128x128, 128 threads (4 warps 2x2), warp tile 64x64, K-chunk 32,
// cp.async double buffer, 3 CTAs/SM (regs capped at 170; B fragments loaded
// just-in-time to keep the live set under the cap).
// Inputs pre-rounded to tf32; no cvt in inner loop.
// EPI: 0 = round(acc), 1 = acc + res, 2 = round(gelu(acc)).
// ---------------------------------------------------------------------------
#define GP     36
#define TILE_F (128 * GP)
#define GSMEM2 (4 * TILE_F * 4)

template <int EPI>
__global__ __launch_bounds__(128, 3)
void gemm_v3(const float* __restrict__ A, const float* __restrict__ B,
             const float* __restrict__ res, float* __restrict__ C,
             int M, int N, int K)
{
    extern __shared__ float sm[];
    const uint32_t sb = smem_u32(sm);

    const int tid  = threadIdx.x;
    const int wid  = tid >> 5, lane = tid & 31;
    const int gid  = lane >> 2, tig = lane & 3;
    const int wm   = (wid & 1) << 6;
    const int wn   = (wid >> 1) << 6;
    const int bm   = blockIdx.y << 7, bn = blockIdx.x << 7;

    const int lr = tid >> 3;             // 0..15
    const int lc = (tid & 7) << 2;       // 0,4,...,28
    const float* Ag = A + (size_t)(bm + lr) * K + lc;
    const float* Bg = B + (size_t)(bn + lr) * K + lc;
    uint32_t so[8];
#pragma unroll
    for (int p = 0; p < 8; p++)
        so[p] = (uint32_t)((p * 16 + lr) * GP + lc) * 4u;

    const uint32_t aB[2] = { sb,                sb + 2u * TILE_F * 4u };
    const uint32_t bB[2] = { sb + TILE_F * 4u,  sb + 3u * TILE_F * 4u };
    const float* Abuf[2] = { sm,             sm + 2 * TILE_F };
    const float* Bbuf[2] = { sm + TILE_F,    sm + 3 * TILE_F };

    float acc[4][8][4];
#pragma unroll
    for (int i = 0; i < 4; i++)
#pragma unroll
        for (int j = 0; j < 8; j++)
#pragma unroll
            for (int q = 0; q < 4; q++) acc[i][j][q] = 0.f;

    const int nk = K >> 5;

#pragma unroll
    for (int p = 0; p < 8; p++) {
        cp_async16(aB[0] + so[p], Ag + (size_t)(p * 16) * K);
        cp_async16(bB[0] + so[p], Bg + (size_t)(p * 16) * K);
    }
    cp_commit();

    for (int c = 0; c < nk; c++) {
        if (c + 1 < nk) {
            const int ko = (c + 1) << 5;
            const int nb = (c + 1) & 1;
#pragma unroll
            for (int p = 0; p < 8; p++) {
                cp_async16(aB[nb] + so[p], Ag + (size_t)(p * 16) * K + ko);
                cp_async16(bB[nb] + so[p], Bg + (size_t)(p * 16) * K + ko);
            }
            cp_commit();
            asm volatile("cp.async.wait_group 1;" ::: "memory");
        } else {
            asm volatile("cp.async.wait_group 0;" ::: "memory");
        }
        __syncthreads();

        const float* As = Abuf[c & 1];
        const float* Bs = Bbuf[c & 1];
#pragma unroll
        for (int ks = 0; ks < 4; ks++) {
            const int k0 = ks * 8;
            uint32_t afr[4][4];
#pragma unroll
            for (int mf = 0; mf < 4; mf++) {
                const int r = wm + mf * 16 + gid;
                afr[mf][0] = __float_as_uint(As[(r)     * GP + k0 + tig]);
                afr[mf][1] = __float_as_uint(As[(r + 8) * GP + k0 + tig]);
                afr[mf][2] = __float_as_uint(As[(r)     * GP + k0 + tig + 4]);
                afr[mf][3] = __float_as_uint(As[(r + 8) * GP + k0 + tig + 4]);
            }
            // B fragments just-in-time: 2 live regs instead of 16
#pragma unroll
            for (int nf = 0; nf < 8; nf++) {
                const int n = wn + nf * 8 + gid;
                const uint32_t b0 = __float_as_uint(Bs[n * GP + k0 + tig]);
                const uint32_t b1 = __float_as_uint(Bs[n * GP + k0 + tig + 4]);
#pragma unroll
                for (int mf = 0; mf < 4; mf++)
                    mma_tf32(acc[mf][nf], afr[mf], b0, b1);
            }
        }
        __syncthreads();
    }

#pragma unroll
    for (int mf = 0; mf < 4; mf++) {
        const int row0 = bm + wm + mf * 16 + gid;
#pragma unroll
        for (int nf = 0; nf < 8; nf++) {
            const int col = bn + wn + nf * 8 + 2 * tig;
            float2 v0 = make_float2(acc[mf][nf][0], acc[mf][nf][1]);
            float2 v1 = make_float2(acc[mf][nf][2], acc[mf][nf][3]);
            const size_t i0 = (size_t)row0 * N + col;
            const size_t i1 = (size_t)(row0 + 8) * N + col;
            if (EPI == 0) {
                v0.x = tf32r(v0.x); v0.y = tf32r(v0.y);
                v1.x = tf32r(v1.x); v1.y = tf32r(v1.y);
            }
            if (EPI == 1) {
                const float2 r0 = *(const float2*)(res + i0);
                const float2 r1 = *(const float2*)(res + i1);
                v0.x += r0.x; v0.y += r0.y;
                v1.x += r1.x; v1.y += r1.y;
            }
            if (EPI == 2) {
                v0.x = tf32r(gelu_f(v0.x)); v0.y = tf32r(gelu_f(v0.y));
                v1.x = tf32r(gelu_f(v1.x)); v1.y = tf32r(gelu_f(v1.y));
            }
            *(float2*)(C + i0) = v0;
            *(float2*)(C + i1) = v1;
        }
    }
}

// ---------------------------------------------------------------------------
// Flash attention with tf32 mma.sync (qkv pre-rounded -> no cvt).
// Grid: (T/64, B*H), 128 threads (4 warps). Warp w owns query rows w*16..+15.
// ---------------------------------------------------------------------------
#define AP 68
#define SMEM_ATTN (4 * 64 * AP * 4)

__global__ __launch_bounds__(128)
void attn_mma(const float* __restrict__ qkv, float* __restrict__ y)
{
    extern __shared__ float smA[];
    float* Qs = smA;
    float* Ks = smA + 64 * AP;
    float* Vt = smA + 2 * 64 * AP;
    float* Ps = smA + 3 * 64 * AP;

    const int qb   = gridDim.x - 1 - blockIdx.x;   // heavy tiles first
    const int b    = blockIdx.y >> 4;
    const int h    = blockIdx.y & 15;
    const int tid  = threadIdx.x;
    const int wid  = tid >> 5, lane = tid & 31;
    const int gid  = lane >> 2, tig = lane & 3;
    const int r0   = wid * 16 + gid;

    const float* base = qkv + (size_t)b * TDIM * QKVW + h * HD;

    const int lr  = tid & 63;
    const int lch = (tid >> 6) << 5;
    {
        const float* src = base + (size_t)(qb * 64 + lr) * QKVW + lch;
        float* dst = &Qs[lr * AP + lch];
#pragma unroll
        for (int i = 0; i < 8; i++) {
            float4 v = ((const float4*)src)[i];
            v.x *= 0.125f; v.y *= 0.125f; v.z *= 0.125f; v.w *= 0.125f;
            *(float4*)(dst + 4 * i) = v;
        }
    }

    float oacc[8][4];
#pragma unroll
    for (int nf = 0; nf < 8; nf++)
#pragma unroll
        for (int q = 0; q < 4; q++) oacc[nf][q] = 0.f;
    float m0 = -1e30f, m1 = -1e30f, l0 = 0.f, l1 = 0.f;

    for (int kb = 0; kb <= qb; kb++) {
        __syncthreads();
        {
            const float* ksrc = base + CDIM     + (size_t)(kb * 64 + lr) * QKVW + lch;
            const float* vsrc = base + 2 * CDIM + (size_t)(kb * 64 + lr) * QKVW + lch;
#pragma unroll
            for (int i = 0; i < 8; i++) {
                *(float4*)&Ks[lr * AP + lch + 4 * i] = ((const float4*)ksrc)[i];
                const float4 vv = ((const float4*)vsrc)[i];
                const int d = lch + 4 * i;
                Vt[(d + 0) * AP + lr] = vv.x;
                Vt[(d + 1) * AP + lr] = vv.y;
                Vt[(d + 2) * AP + lr] = vv.z;
                Vt[(d + 3) * AP + lr] = vv.w;
            }
        }
        __syncthreads();

        float sacc[8][4];
#pragma unroll
        for (int nf = 0; nf < 8; nf++)
#pragma unroll
            for (int q = 0; q < 4; q++) sacc[nf][q] = 0.f;
#pragma unroll
        for (int ks = 0; ks < 8; ks++) {
            const int k0 = ks * 8;
            uint32_t a[4];
            a[0] = __float_as_uint(Qs[(r0)     * AP + k0 + tig]);
            a[1] = __float_as_uint(Qs[(r0 + 8) * AP + k0 + tig]);
            a[2] = __float_as_uint(Qs[(r0)     * AP + k0 + tig + 4]);
            a[3] = __float_as_uint(Qs[(r0 + 8) * AP + k0 + tig + 4]);
#pragma unroll
            for (int nf = 0; nf < 8; nf++) {
                const uint32_t b0 = __float_as_uint(Ks[(nf * 8 + gid) * AP + k0 + tig]);
                const uint32_t b1 = __float_as_uint(Ks[(nf * 8 + gid) * AP + k0 + tig + 4]);
                mma_tf32(sacc[nf], a, b0, b1);
            }
        }

        if (kb == qb) {
#pragma unroll
            for (int nf = 0; nf < 8; nf++) {
                const int c0 = nf * 8 + 2 * tig;
                if (c0     > r0)     sacc[nf][0] = -1e30f;
                if (c0 + 1 > r0)     sacc[nf][1] = -1e30f;
                if (c0     > r0 + 8) sacc[nf][2] = -1e30f;
                if (c0 + 1 > r0 + 8) sacc[nf][3] = -1e30f;
            }
        }

        float mx0 = -1e30f, mx1 = -1e30f;
#pragma unroll
        for (int nf = 0; nf < 8; nf++) {
            mx0 = fmaxf(mx0, fmaxf(sacc[nf][0], sacc[nf][1]));
            mx1 = fmaxf(mx1, fmaxf(sacc[nf][2], sacc[nf][3]));
        }
        mx0 = fmaxf(mx0, __shfl_xor_sync(0xffffffffu, mx0, 1));
        mx0 = fmaxf(mx0, __shfl_xor_sync(0xffffffffu, mx0, 2));
        mx1 = fmaxf(mx1, __shfl_xor_sync(0xffffffffu, mx1, 1));
        mx1 = fmaxf(mx1, __shfl_xor_sync(0xffffffffu, mx1, 2));
        const float mn0 = fmaxf(m0, mx0), mn1 = fmaxf(m1, mx1);
        const float al0 = __expf(m0 - mn0), al1 = __expf(m1 - mn1);
        float rs0 = 0.f, rs1 = 0.f;
#pragma unroll
        for (int nf = 0; nf < 8; nf++) {
            const float p0 = tf32r(__expf(sacc[nf][0] - mn0));
            const float p1 = tf32r(__expf(sacc[nf][1] - mn0));
            const float p2 = tf32r(__expf(sacc[nf][2] - mn1));
            const float p3 = tf32r(__expf(sacc[nf][3] - mn1));
            rs0 += p0 + p1;
            rs1 += p2 + p3;
            const int c = nf * 8 + 2 * tig;
            *(float2*)&Ps[(r0)     * AP + c] = make_float2(p0, p1);
            *(float2*)&Ps[(r0 + 8) * AP + c] = make_float2(p2, p3);
        }
        rs0 += __shfl_xor_sync(0xffffffffu, rs0, 1);
        rs0 += __shfl_xor_sync(0xffffffffu, rs0, 2);
        rs1 += __shfl_xor_sync(0xffffffffu, rs1, 1);
        rs1 += __shfl_xor_sync(0xffffffffu, rs1, 2);
        l0 = l0 * al0 + rs0;  m0 = mn0;
        l1 = l1 * al1 + rs1;  m1 = mn1;
#pragma unroll
        for (int nf = 0; nf < 8; nf++) {
            oacc[nf][0] *= al0; oacc[nf][1] *= al0;
            oacc[nf][2] *= al1; oacc[nf][3] *= al1;
        }
        __syncwarp();

#pragma unroll
        for (int ks = 0; ks < 8; ks++) {
            const int k0 = ks * 8;
            uint32_t a[4];
            a[0] = __float_as_uint(Ps[(r0)     * AP + k0 + tig]);
            a[1] = __float_as_uint(Ps[(r0 + 8) * AP + k0 + tig]);
            a[2] = __float_as_uint(Ps[(r0)     * AP + k0 + tig + 4]);
            a[3] = __float_as_uint(Ps[(r0 + 8) * AP + k0 + tig + 4]);
#pragma unroll
            for (int nf = 0; nf < 8; nf++) {
                const uint32_t b0 = __float_as_uint(Vt[(nf * 8 + gid) * AP + k0 + tig]);
                const uint32_t b1 = __float_as_uint(Vt[(nf * 8 + gid) * AP + k0 + tig + 4]);
                mma_tf32(oacc[nf], a, b0, b1);
            }
        }
    }

    const float inv0 = 1.0f / l0, inv1 = 1.0f / l1;
    float* dst0 = y + (size_t)(b * TDIM + qb * 64 + r0) * CDIM + h * HD;
    float* dst1 = dst0 + 8 * CDIM;
#pragma unroll
    for (int nf = 0; nf < 8; nf++) {
        const int c = nf * 8 + 2 * tig;
        *(float2*)(dst0 + c) = make_float2(tf32r(oacc[nf][0] * inv0),
                                           tf32r(oacc[nf][1] * inv0));
        *(float2*)(dst1 + c) = make_float2(tf32r(oacc[nf][2] * inv1),
                                           tf32r(oacc[nf][3] * inv1));
    }
}

// ---------------------------------------------------------------------------
// Launch orchestration (graph-capturable)
// ---------------------------------------------------------------------------
extern "C" void kernel_launch(void* const* d_in, const int* in_sizes, int n_in,
                              void* d_out, int out_size)
{
    const float* x      = (const float*)d_in[0];
    const float* g1     = (const float*)d_in[1];
    const float* w_qkv  = (const float*)d_in[2];
    const float* w_o    = (const float*)d_in[3];
    const float* g2     = (const float*)d_in[4];
    const float* w_fc   = (const float*)d_in[5];
    const float* w_proj = (const float*)d_in[6];
    float* out = (float*)d_out;

    float *ln, *qkvb, *yb, *x2, *hb, *wq, *wo, *wfc, *wp;
    cudaGetSymbolAddress((void**)&ln,   g_ln);
    cudaGetSymbolAddress((void**)&qkvb, g_qkv);
    cudaGetSymbolAddress((void**)&yb,   g_y);
    cudaGetSymbolAddress((void**)&x2,   g_x2);
    cudaGetSymbolAddress((void**)&hb,   g_h);
    cudaGetSymbolAddress((void**)&wq,   g_wq);
    cudaGetSymbolAddress((void**)&wo,   g_wo);
    cudaGetSymbolAddress((void**)&wfc,  g_wfc);
    cudaGetSymbolAddress((void**)&wp,   g_wp);

    cudaFuncSetAttribute(attn_mma,
                         cudaFuncAttributeMaxDynamicSharedMemorySize, SMEM_ATTN);
    cudaFuncSetAttribute(gemm_v3<0>,
                         cudaFuncAttributeMaxDynamicSharedMemorySize, GSMEM2);
    cudaFuncSetAttribute(gemm_v3<1>,
                         cudaFuncAttributeMaxDynamicSharedMemorySize, GSMEM2);
    cudaFuncSetAttribute(gemm_v3<2>,
                         cudaFuncAttributeMaxDynamicSharedMemorySize, GSMEM2);

    // Round weights to tf32 once per launch
    round_tf32_kernel<<<(QKVW * CDIM / 4 + 255) / 256, 256>>>(w_qkv, wq,
                                                              QKVW * CDIM / 4);
    round_tf32_kernel<<<(CDIM * CDIM / 4 + 255) / 256, 256>>>(w_o, wo,
                                                              CDIM * CDIM / 4);
    round_tf32_kernel<<<(FFDIM * CDIM / 4 + 255) / 256, 256>>>(w_fc, wfc,
                                                               FFDIM * CDIM / 4);
    round_tf32_kernel<<<(CDIM * FFDIM / 4 + 255) / 256, 256>>>(w_proj, wp,
                                                               CDIM * FFDIM / 4);

    // x1 = ln1(x); qkv = x1 @ Wqkv^T  (output rounded)
    ln_kernel<<<BT, 256>>>(x, g1, ln);
    gemm_v3<0><<<dim3(QKVW / 128, BT / 128), 128, GSMEM2>>>(
        ln, wq, nullptr, qkvb, BT, QKVW, CDIM);
    // y = causal attention (tf32 mma; output rounded)
    attn_mma<<<dim3(TDIM / 64, BDIM * HEADS), 128, SMEM_ATTN>>>(qkvb, yb);
    // x2 = x + y @ Wo^T
    gemm_v3<1><<<dim3(CDIM / 128, BT / 128), 128, GSMEM2>>>(
        yb, wo, x, x2, BT, CDIM, CDIM);
    // h = gelu(ln2(x2) @ Wfc^T)  (output rounded)
    ln_kernel<<<BT, 256>>>(x2, g2, ln);
    gemm_v3<2><<<dim3(FFDIM / 128, BT / 128), 128, GSMEM2>>>(
        ln, wfc, nullptr, hb, BT, FFDIM, CDIM);
    // out = x2 + h @ Wproj^T
    gemm_v3<1><<<dim3(CDIM / 128, BT / 128), 128, GSMEM2>>>(
        hb, wp, x2, out, BT, CDIM, FFDIM);
}

// round 7
// speedup vs baseline: 1.1439x; 1.1439x over previous
#include <cuda_runtime.h>
#include <math.h>
#include <stdint.h>

// Problem constants
#define BDIM   4
#define TDIM   2048
#define CDIM   1024
#define HEADS  16
#define HD     64
#define FFDIM  4096
#define BT     8192            // B*T rows
#define QKVW   3072            // 3*C

// ---------------------------------------------------------------------------
// Scratch (no allocations allowed — __device__ globals)
// ---------------------------------------------------------------------------
__device__ float g_ln [BT * CDIM];
__device__ float g_qkv[BT * QKVW];
__device__ float g_y  [BT * CDIM];
__device__ float g_x2 [BT * CDIM];
__device__ float g_h  [BT * FFDIM];
// tf32-rounded weights
__device__ float g_wq [QKVW * CDIM];
__device__ float g_wo [CDIM * CDIM];
__device__ float g_wfc[FFDIM * CDIM];
__device__ float g_wp [CDIM * FFDIM];

// ---------------------------------------------------------------------------
// Helpers
// ---------------------------------------------------------------------------
__device__ __forceinline__ uint32_t f2tf32(float f) {
    uint32_t u;
    asm("cvt.rna.tf32.f32 %0, %1;" : "=r"(u) : "f"(f));
    return u;
}
__device__ __forceinline__ float tf32r(float f) {
    return __uint_as_float(f2tf32(f));
}
__device__ __forceinline__ uint32_t smem_u32(const void* p) {
    uint32_t a;
    asm("{ .reg .u64 t; cvta.to.shared.u64 t, %1; cvt.u32.u64 %0, t; }"
        : "=r"(a) : "l"(p));
    return a;
}
__device__ __forceinline__ void cp_async16(uint32_t saddr, const void* gaddr) {
    asm volatile("cp.async.cg.shared.global [%0], [%1], 16;"
                 :: "r"(saddr), "l"(gaddr) : "memory");
}
__device__ __forceinline__ void cp_commit() {
    asm volatile("cp.async.commit_group;" ::: "memory");
}
__device__ __forceinline__ void ldsm_x4(uint32_t& r0, uint32_t& r1,
                                        uint32_t& r2, uint32_t& r3,
                                        uint32_t addr) {
    asm volatile("ldmatrix.sync.aligned.m8n8.x4.shared.b16 {%0,%1,%2,%3}, [%4];"
                 : "=r"(r0), "=r"(r1), "=r"(r2), "=r"(r3) : "r"(addr));
}
__device__ __forceinline__ void mma_tf32(float* d, const uint32_t* a,
                                         uint32_t b0, uint32_t b1) {
    asm volatile(
        "mma.sync.aligned.m16n8k8.row.col.f32.tf32.tf32.f32 "
        "{%0,%1,%2,%3}, {%4,%5,%6,%7}, {%8,%9}, {%0,%1,%2,%3};"
        : "+f"(d[0]), "+f"(d[1]), "+f"(d[2]), "+f"(d[3])
        : "r"(a[0]), "r"(a[1]), "r"(a[2]), "r"(a[3]), "r"(b0), "r"(b1));
}
__device__ __forceinline__ float gelu_f(float v) {
    return 0.5f * v * (1.0f + erff(v * 0.70710678118654752f));
}

// ---------------------------------------------------------------------------
// Weight prep: round to tf32 once
// ---------------------------------------------------------------------------
__global__ __launch_bounds__(256)
void round_tf32_kernel(const float* __restrict__ src, float* __restrict__ dst,
                       int n4)
{
    const int i = blockIdx.x * blockDim.x + threadIdx.x;
    if (i < n4) {
        float4 v = ((const float4*)src)[i];
        v.x = tf32r(v.x); v.y = tf32r(v.y);
        v.z = tf32r(v.z); v.w = tf32r(v.w);
        ((float4*)dst)[i] = v;
    }
}

// ---------------------------------------------------------------------------
// LayerNorm: one block per row, C=1024, 256 threads x float4 (tf32 output)
// ---------------------------------------------------------------------------
__global__ __launch_bounds__(256)
void ln_kernel(const float* __restrict__ x, const float* __restrict__ g,
               float* __restrict__ y)
{
    const int row = blockIdx.x;
    const int tid = threadIdx.x;
    const float4 v = ((const float4*)(x + (size_t)row * CDIM))[tid];
    float s  = v.x + v.y + v.z + v.w;
    float ss = v.x * v.x + v.y * v.y + v.z * v.z + v.w * v.w;
#pragma unroll
    for (int o = 16; o > 0; o >>= 1) {
        s  += __shfl_xor_sync(0xffffffffu, s,  o);
        ss += __shfl_xor_sync(0xffffffffu, ss, o);
    }
    __shared__ float rs[8], rss[8];
    const int w = tid >> 5, lane = tid & 31;
    if (lane == 0) { rs[w] = s; rss[w] = ss; }
    __syncthreads();
    if (tid == 0) {
        float a = 0.f, b = 0.f;
#pragma unroll
        for (int i = 0; i < 8; i++) { a += rs[i]; b += rss[i]; }
        const float mean = a * (1.0f / CDIM);
        const float var  = b * (1.0f / CDIM) - mean * mean;
        rs[0]  = mean;
        rss[0] = rsqrtf(var + 1e-5f);
    }
    __syncthreads();
    const float mean = rs[0], rstd = rss[0];
    const float4 gv = ((const float4*)g)[tid];
    float4 o4;
    o4.x = tf32r((v.x - mean) * rstd * gv.x);
    o4.y = tf32r((v.y - mean) * rstd * gv.y);
    o4.z = tf32r((v.z - mean) * rstd * gv.z);
    o4.w = tf32r((v.w - mean) * rstd * gv.w);
    ((float4*)(y + (size_t)row * CDIM))[tid] = o4;
}

// ---------------------------------------------------------------------------
// TF32 mma.sync GEMM v4 (NT): C[m,n] = sum_k A[m,k]*B[n,k]
// CTA 128x128, 128 threads (4 warps 2x2), warp tile 64x64, K-chunk 32,
// cp.async double buffer, fragments loaded via ldmatrix.x4 (8 LDSM per
// k-step instead of 32 LDS). Inputs pre-rounded to tf32.
// EPI: 0 = round(acc), 1 = acc + res, 2 = round(gelu(acc)).
// ---------------------------------------------------------------------------
#define GP     36
#define TILE_F (128 * GP)
#define GSMEM2 (4 * TILE_F * 4)

template <int EPI>
__global__ __launch_bounds__(128, 2)
void gemm_v4(const float* __restrict__ A, const float* __restrict__ B,
             const float* __restrict__ res, float* __restrict__ C,
             int M, int N, int K)
{
    extern __shared__ float sm[];
    const uint32_t sb = smem_u32(sm);

    const int tid  = threadIdx.x;
    const int wid  = tid >> 5, lane = tid & 31;
    const int gid  = lane >> 2, tig = lane & 3;
    const int wm   = (wid & 1) << 6;     // 0 / 64 row slab
    const int wn   = (wid >> 1) << 6;    // 0 / 64 col slab
    const int bm   = blockIdx.y << 7, bn = blockIdx.x << 7;

    // cp.async map: 8 x 16B per operand tile per thread
    const int lr = tid >> 3;             // 0..15
    const int lc = (tid & 7) << 2;       // 0,4,...,28
    const float* Ag = A + (size_t)(bm + lr) * K + lc;
    const float* Bg = B + (size_t)(bn + lr) * K + lc;
    uint32_t so[8];
#pragma unroll
    for (int p = 0; p < 8; p++)
        so[p] = (uint32_t)((p * 16 + lr) * GP + lc) * 4u;

    const uint32_t aB[2] = { sb,                sb + 2u * TILE_F * 4u };
    const uint32_t bB[2] = { sb + TILE_F * 4u,  sb + 3u * TILE_F * 4u };

    // ldmatrix lane->address maps (byte offsets within a tile buffer)
    // A (per mf,ks): matrices {rows 0-7 k0..3, rows 8-15 k0..3,
    //                          rows 0-7 k0+4.., rows 8-15 k0+4..}
    const int aRow = wm + (lane & 7) + ((lane >> 3) & 1) * 8;
    const uint32_t aMap = (uint32_t)(aRow * GP + (lane >> 4) * 4) * 4u;
    // B (per nf-pair p,ks): matrices {nf rows k0, nf rows k0+4,
    //                                 nf+1 rows k0, nf+1 rows k0+4}
    const int bRow = wn + (lane >> 4) * 8 + (lane & 7);
    const uint32_t bMap = (uint32_t)(bRow * GP + ((lane >> 3) & 1) * 4) * 4u;

    float acc[4][8][4];
#pragma unroll
    for (int i = 0; i < 4; i++)
#pragma unroll
        for (int j = 0; j < 8; j++)
#pragma unroll
            for (int q = 0; q < 4; q++) acc[i][j][q] = 0.f;

    const int nk = K >> 5;

#pragma unroll
    for (int p = 0; p < 8; p++) {
        cp_async16(aB[0] + so[p], Ag + (size_t)(p * 16) * K);
        cp_async16(bB[0] + so[p], Bg + (size_t)(p * 16) * K);
    }
    cp_commit();

    for (int c = 0; c < nk; c++) {
        if (c + 1 < nk) {
            const int ko = (c + 1) << 5;
            const int nb = (c + 1) & 1;
#pragma unroll
            for (int p = 0; p < 8; p++) {
                cp_async16(aB[nb] + so[p], Ag + (size_t)(p * 16) * K + ko);
                cp_async16(bB[nb] + so[p], Bg + (size_t)(p * 16) * K + ko);
            }
            cp_commit();
            asm volatile("cp.async.wait_group 1;" ::: "memory");
        } else {
            asm volatile("cp.async.wait_group 0;" ::: "memory");
        }
        __syncthreads();

        const uint32_t aBase = aB[c & 1] + aMap;
        const uint32_t bBase = bB[c & 1] + bMap;
#pragma unroll
        for (int ks = 0; ks < 4; ks++) {
            uint32_t afr[4][4], bfr[8][2];
#pragma unroll
            for (int mf = 0; mf < 4; mf++)
                ldsm_x4(afr[mf][0], afr[mf][1], afr[mf][2], afr[mf][3],
                        aBase + (uint32_t)((mf * 16 * GP + ks * 8) * 4));
#pragma unroll
            for (int p = 0; p < 4; p++)
                ldsm_x4(bfr[2 * p][0], bfr[2 * p][1],
                        bfr[2 * p + 1][0], bfr[2 * p + 1][1],
                        bBase + (uint32_t)((p * 16 * GP + ks * 8) * 4));
#pragma unroll
            for (int mf = 0; mf < 4; mf++)
#pragma unroll
                for (int nf = 0; nf < 8; nf++)
                    mma_tf32(acc[mf][nf], afr[mf], bfr[nf][0], bfr[nf][1]);
        }
        __syncthreads();
    }

#pragma unroll
    for (int mf = 0; mf < 4; mf++) {
        const int row0 = bm + wm + mf * 16 + gid;
#pragma unroll
        for (int nf = 0; nf < 8; nf++) {
            const int col = bn + wn + nf * 8 + 2 * tig;
            float2 v0 = make_float2(acc[mf][nf][0], acc[mf][nf][1]);
            float2 v1 = make_float2(acc[mf][nf][2], acc[mf][nf][3]);
            const size_t i0 = (size_t)row0 * N + col;
            const size_t i1 = (size_t)(row0 + 8) * N + col;
            if (EPI == 0) {
                v0.x = tf32r(v0.x); v0.y = tf32r(v0.y);
                v1.x = tf32r(v1.x); v1.y = tf32r(v1.y);
            }
            if (EPI == 1) {
                const float2 r0 = *(const float2*)(res + i0);
                const float2 r1 = *(const float2*)(res + i1);
                v0.x += r0.x; v0.y += r0.y;
                v1.x += r1.x; v1.y += r1.y;
            }
            if (EPI == 2) {
                v0.x = tf32r(gelu_f(v0.x)); v0.y = tf32r(gelu_f(v0.y));
                v1.x = tf32r(gelu_f(v1.x)); v1.y = tf32r(gelu_f(v1.y));
            }
            *(float2*)(C + i0) = v0;
            *(float2*)(C + i1) = v1;
        }
    }
}

// ---------------------------------------------------------------------------
// Flash attention with tf32 mma.sync (qkv pre-rounded -> no cvt).
// Grid: (T/64, B*H), 128 threads (4 warps). Warp w owns query rows w*16..+15.
// ---------------------------------------------------------------------------
#define AP 68
#define SMEM_ATTN (4 * 64 * AP * 4)

__global__ __launch_bounds__(128)
void attn_mma(const float* __restrict__ qkv, float* __restrict__ y)
{
    extern __shared__ float smA[];
    float* Qs = smA;
    float* Ks = smA + 64 * AP;
    float* Vt = smA + 2 * 64 * AP;
    float* Ps = smA + 3 * 64 * AP;

    const int qb   = gridDim.x - 1 - blockIdx.x;   // heavy tiles first
    const int b    = blockIdx.y >> 4;
    const int h    = blockIdx.y & 15;
    const int tid  = threadIdx.x;
    const int wid  = tid >> 5, lane = tid & 31;
    const int gid  = lane >> 2, tig = lane & 3;
    const int r0   = wid * 16 + gid;

    const float* base = qkv + (size_t)b * TDIM * QKVW + h * HD;

    const int lr  = tid & 63;
    const int lch = (tid >> 6) << 5;
    {
        const float* src = base + (size_t)(qb * 64 + lr) * QKVW + lch;
        float* dst = &Qs[lr * AP + lch];
#pragma unroll
        for (int i = 0; i < 8; i++) {
            float4 v = ((const float4*)src)[i];
            v.x *= 0.125f; v.y *= 0.125f; v.z *= 0.125f; v.w *= 0.125f;
            *(float4*)(dst + 4 * i) = v;
        }
    }

    float oacc[8][4];
#pragma unroll
    for (int nf = 0; nf < 8; nf++)
#pragma unroll
        for (int q = 0; q < 4; q++) oacc[nf][q] = 0.f;
    float m0 = -1e30f, m1 = -1e30f, l0 = 0.f, l1 = 0.f;

    for (int kb = 0; kb <= qb; kb++) {
        __syncthreads();
        {
            const float* ksrc = base + CDIM     + (size_t)(kb * 64 + lr) * QKVW + lch;
            const float* vsrc = base + 2 * CDIM + (size_t)(kb * 64 + lr) * QKVW + lch;
#pragma unroll
            for (int i = 0; i < 8; i++) {
                *(float4*)&Ks[lr * AP + lch + 4 * i] = ((const float4*)ksrc)[i];
                const float4 vv = ((const float4*)vsrc)[i];
                const int d = lch + 4 * i;
                Vt[(d + 0) * AP + lr] = vv.x;
                Vt[(d + 1) * AP + lr] = vv.y;
                Vt[(d + 2) * AP + lr] = vv.z;
                Vt[(d + 3) * AP + lr] = vv.w;
            }
        }
        __syncthreads();

        float sacc[8][4];
#pragma unroll
        for (int nf = 0; nf < 8; nf++)
#pragma unroll
            for (int q = 0; q < 4; q++) sacc[nf][q] = 0.f;
#pragma unroll
        for (int ks = 0; ks < 8; ks++) {
            const int k0 = ks * 8;
            uint32_t a[4];
            a[0] = __float_as_uint(Qs[(r0)     * AP + k0 + tig]);
            a[1] = __float_as_uint(Qs[(r0 + 8) * AP + k0 + tig]);
            a[2] = __float_as_uint(Qs[(r0)     * AP + k0 + tig + 4]);
            a[3] = __float_as_uint(Qs[(r0 + 8) * AP + k0 + tig + 4]);
#pragma unroll
            for (int nf = 0; nf < 8; nf++) {
                const uint32_t b0 = __float_as_uint(Ks[(nf * 8 + gid) * AP + k0 + tig]);
                const uint32_t b1 = __float_as_uint(Ks[(nf * 8 + gid) * AP + k0 + tig + 4]);
                mma_tf32(sacc[nf], a, b0, b1);
            }
        }

        if (kb == qb) {
#pragma unroll
            for (int nf = 0; nf < 8; nf++) {
                const int c0 = nf * 8 + 2 * tig;
                if (c0     > r0)     sacc[nf][0] = -1e30f;
                if (c0 + 1 > r0)     sacc[nf][1] = -1e30f;
                if (c0     > r0 + 8) sacc[nf][2] = -1e30f;
                if (c0 + 1 > r0 + 8) sacc[nf][3] = -1e30f;
            }
        }

        float mx0 = -1e30f, mx1 = -1e30f;
#pragma unroll
        for (int nf = 0; nf < 8; nf++) {
            mx0 = fmaxf(mx0, fmaxf(sacc[nf][0], sacc[nf][1]));
            mx1 = fmaxf(mx1, fmaxf(sacc[nf][2], sacc[nf][3]));
        }
        mx0 = fmaxf(mx0, __shfl_xor_sync(0xffffffffu, mx0, 1));
        mx0 = fmaxf(mx0, __shfl_xor_sync(0xffffffffu, mx0, 2));
        mx1 = fmaxf(mx1, __shfl_xor_sync(0xffffffffu, mx1, 1));
        mx1 = fmaxf(mx1, __shfl_xor_sync(0xffffffffu, mx1, 2));
        const float mn0 = fmaxf(m0, mx0), mn1 = fmaxf(m1, mx1);
        const float al0 = __expf(m0 - mn0), al1 = __expf(m1 - mn1);
        float rs0 = 0.f, rs1 = 0.f;
#pragma unroll
        for (int nf = 0; nf < 8; nf++) {
            const float p0 = tf32r(__expf(sacc[nf][0] - mn0));
            const float p1 = tf32r(__expf(sacc[nf][1] - mn0));
            const float p2 = tf32r(__expf(sacc[nf][2] - mn1));
            const float p3 = tf32r(__expf(sacc[nf][3] - mn1));
            rs0 += p0 + p1;
            rs1 += p2 + p3;
            const int c = nf * 8 + 2 * tig;
            *(float2*)&Ps[(r0)     * AP + c] = make_float2(p0, p1);
            *(float2*)&Ps[(r0 + 8) * AP + c] = make_float2(p2, p3);
        }
        rs0 += __shfl_xor_sync(0xffffffffu, rs0, 1);
        rs0 += __shfl_xor_sync(0xffffffffu, rs0, 2);
        rs1 += __shfl_xor_sync(0xffffffffu, rs1, 1);
        rs1 += __shfl_xor_sync(0xffffffffu, rs1, 2);
        l0 = l0 * al0 + rs0;  m0 = mn0;
        l1 = l1 * al1 + rs1;  m1 = mn1;
#pragma unroll
        for (int nf = 0; nf < 8; nf++) {
            oacc[nf][0] *= al0; oacc[nf][1] *= al0;
            oacc[nf][2] *= al1; oacc[nf][3] *= al1;
        }
        __syncwarp();

#pragma unroll
        for (int ks = 0; ks < 8; ks++) {
            const int k0 = ks * 8;
            uint32_t a[4];
            a[0] = __float_as_uint(Ps[(r0)     * AP + k0 + tig]);
            a[1] = __float_as_uint(Ps[(r0 + 8) * AP + k0 + tig]);
            a[2] = __float_as_uint(Ps[(r0)     * AP + k0 + tig + 4]);
            a[3] = __float_as_uint(Ps[(r0 + 8) * AP + k0 + tig + 4]);
#pragma unroll
            for (int nf = 0; nf < 8; nf++) {
                const uint32_t b0 = __float_as_uint(Vt[(nf * 8 + gid) * AP + k0 + tig]);
                const uint32_t b1 = __float_as_uint(Vt[(nf * 8 + gid) * AP + k0 + tig + 4]);
                mma_tf32(oacc[nf], a, b0, b1);
            }
        }
    }

    const float inv0 = 1.0f / l0, inv1 = 1.0f / l1;
    float* dst0 = y + (size_t)(b * TDIM + qb * 64 + r0) * CDIM + h * HD;
    float* dst1 = dst0 + 8 * CDIM;
#pragma unroll
    for (int nf = 0; nf < 8; nf++) {
        const int c = nf * 8 + 2 * tig;
        *(float2*)(dst0 + c) = make_float2(tf32r(oacc[nf][0] * inv0),
                                           tf32r(oacc[nf][1] * inv0));
        *(float2*)(dst1 + c) = make_float2(tf32r(oacc[nf][2] * inv1),
                                           tf32r(oacc[nf][3] * inv1));
    }
}

// ---------------------------------------------------------------------------
// Launch orchestration (graph-capturable)
// ---------------------------------------------------------------------------
extern "C" void kernel_launch(void* const* d_in, const int* in_sizes, int n_in,
                              void* d_out, int out_size)
{
    const float* x      = (const float*)d_in[0];
    const float* g1     = (const float*)d_in[1];
    const float* w_qkv  = (const float*)d_in[2];
    const float* w_o    = (const float*)d_in[3];
    const float* g2     = (const float*)d_in[4];
    const float* w_fc   = (const float*)d_in[5];
    const float* w_proj = (const float*)d_in[6];
    float* out = (float*)d_out;

    float *ln, *qkvb, *yb, *x2, *hb, *wq, *wo, *wfc, *wp;
    cudaGetSymbolAddress((void**)&ln,   g_ln);
    cudaGetSymbolAddress((void**)&qkvb, g_qkv);
    cudaGetSymbolAddress((void**)&yb,   g_y);
    cudaGetSymbolAddress((void**)&x2,   g_x2);
    cudaGetSymbolAddress((void**)&hb,   g_h);
    cudaGetSymbolAddress((void**)&wq,   g_wq);
    cudaGetSymbolAddress((void**)&wo,   g_wo);
    cudaGetSymbolAddress((void**)&wfc,  g_wfc);
    cudaGetSymbolAddress((void**)&wp,   g_wp);

    cudaFuncSetAttribute(attn_mma,
                         cudaFuncAttributeMaxDynamicSharedMemorySize, SMEM_ATTN);
    cudaFuncSetAttribute(gemm_v4<0>,
                         cudaFuncAttributeMaxDynamicSharedMemorySize, GSMEM2);
    cudaFuncSetAttribute(gemm_v4<1>,
                         cudaFuncAttributeMaxDynamicSharedMemorySize, GSMEM2);
    cudaFuncSetAttribute(gemm_v4<2>,
                         cudaFuncAttributeMaxDynamicSharedMemorySize, GSMEM2);

    // Round weights to tf32 once per launch
    round_tf32_kernel<<<(QKVW * CDIM / 4 + 255) / 256, 256>>>(w_qkv, wq,
                                                              QKVW * CDIM / 4);
    round_tf32_kernel<<<(CDIM * CDIM / 4 + 255) / 256, 256>>>(w_o, wo,
                                                              CDIM * CDIM / 4);
    round_tf32_kernel<<<(FFDIM * CDIM / 4 + 255) / 256, 256>>>(w_fc, wfc,
                                                               FFDIM * CDIM / 4);
    round_tf32_kernel<<<(CDIM * FFDIM / 4 + 255) / 256, 256>>>(w_proj, wp,
                                                               CDIM * FFDIM / 4);

    // x1 = ln1(x); qkv = x1 @ Wqkv^T  (output rounded)
    ln_kernel<<<BT, 256>>>(x, g1, ln);
    gemm_v4<0><<<dim3(QKVW / 128, BT / 128), 128, GSMEM2>>>(
        ln, wq, nullptr, qkvb, BT, QKVW, CDIM);
    // y = causal attention (tf32 mma; output rounded)
    attn_mma<<<dim3(TDIM / 64, BDIM * HEADS), 128, SMEM_ATTN>>>(qkvb, yb);
    // x2 = x + y @ Wo^T
    gemm_v4<1><<<dim3(CDIM / 128, BT / 128), 128, GSMEM2>>>(
        yb, wo, x, x2, BT, CDIM, CDIM);
    // h = gelu(ln2(x2) @ Wfc^T)  (output rounded)
    ln_kernel<<<BT, 256>>>(x2, g2, ln);
    gemm_v4<2><<<dim3(FFDIM / 128, BT / 128), 128, GSMEM2>>>(
        ln, wfc, nullptr, hb, BT, FFDIM, CDIM);
    // out = x2 + h @ Wproj^T
    gemm_v4<1><<<dim3(CDIM / 128, BT / 128), 128, GSMEM2>>>(
        hb, wp, x2, out, BT, CDIM, FFDIM);
}